// round 1
// baseline (speedup 1.0000x reference)
#include <cuda_runtime.h>
#include <math.h>

#define SEQ   1024
#define BATCH 2
#define HID   768
#define NHEAD 12
#define HDIM  64
#define FFD   3072
#define MTOT  (BATCH*SEQ)   // 2048
#define BHTOT (BATCH*NHEAD) // 24

// ---------------- scratch (device globals: no allocation allowed) ----------------
__device__ float g_x [MTOT*HID];
__device__ float g_q [MTOT*HID];
__device__ float g_k [MTOT*HID];
__device__ float g_v [MTOT*HID];
__device__ float g_ao[MTOT*HID];
__device__ float g_r1[MTOT*HID];
__device__ float g_y [MTOT*HID];
__device__ float g_ff[MTOT*FFD];

// ---------------- LayerNorm: one block per row of 768 ----------------
__global__ void ln_kernel(const float* __restrict__ in, const float* __restrict__ g,
                          const float* __restrict__ b, float* __restrict__ out) {
    int row = blockIdx.x;
    const float* x = in + (size_t)row * HID;
    int t = threadIdx.x;
    float v0 = x[t], v1 = x[t + 256], v2 = x[t + 512];
    float s  = v0 + v1 + v2;
    float sq = v0 * v0 + v1 * v1 + v2 * v2;
    __shared__ float sh[16];
    #pragma unroll
    for (int o = 16; o; o >>= 1) {
        s  += __shfl_xor_sync(0xffffffffu, s,  o);
        sq += __shfl_xor_sync(0xffffffffu, sq, o);
    }
    int w = t >> 5, l = t & 31;
    if (!l) { sh[w] = s; sh[w + 8] = sq; }
    __syncthreads();
    if (w == 0) {
        float a = (l < 8) ? sh[l] : 0.f;
        float c = (l < 8) ? sh[l + 8] : 0.f;
        #pragma unroll
        for (int o = 4; o; o >>= 1) {
            a += __shfl_xor_sync(0xffffffffu, a, o);
            c += __shfl_xor_sync(0xffffffffu, c, o);
        }
        if (!l) { sh[0] = a; sh[1] = c; }
    }
    __syncthreads();
    float mean = sh[0] * (1.f / HID);
    float var  = sh[1] * (1.f / HID) - mean * mean;
    float rs   = rsqrtf(var + 1e-5f);
    float* o = out + (size_t)row * HID;
    o[t]       = (v0 - mean) * rs * g[t]       + b[t];
    o[t + 256] = (v1 - mean) * rs * g[t + 256] + b[t + 256];
    o[t + 512] = (v2 - mean) * rs * g[t + 512] + b[t + 512];
}

// ---------------- sgemm: C = A[M,K] @ B[K,N] + bias (+res / gelu) ----------------
// BM=BN=128, BK=8, 256 threads, 8x8 microtile. M%128==0, N%128==0, K%8==0 required.
// mode: 0 = +bias, 1 = +bias+res, 2 = gelu(+bias)
__global__ void __launch_bounds__(256) sgemm_kernel(
    const float* __restrict__ A, const float* __restrict__ Bm,
    const float* __restrict__ bias, const float* __restrict__ res,
    float* __restrict__ C, int M, int N, int K, int mode)
{
    __shared__ float As[8][128];
    __shared__ float Bs[8][128];
    int tid = threadIdx.x;
    int bm = blockIdx.y * 128, bn = blockIdx.x * 128;
    int arow = tid >> 1, acol = (tid & 1) * 4;
    int brow = tid >> 5, bcol = (tid & 31) * 4;
    int tx = tid & 15, ty = tid >> 4;
    int ms = ty * 8, ns = tx * 8;

    float acc[8][8];
    #pragma unroll
    for (int i = 0; i < 8; i++)
        #pragma unroll
        for (int j = 0; j < 8; j++) acc[i][j] = 0.f;

    const float* Ap = A  + (size_t)(bm + arow) * K + acol;
    const float* Bp = Bm + (size_t)brow * N + bn + bcol;

    for (int k0 = 0; k0 < K; k0 += 8) {
        float4 av = *(const float4*)(Ap + k0);
        float4 bv = *(const float4*)(Bp + (size_t)k0 * N);
        __syncthreads();
        As[acol + 0][arow] = av.x;
        As[acol + 1][arow] = av.y;
        As[acol + 2][arow] = av.z;
        As[acol + 3][arow] = av.w;
        *(float4*)&Bs[brow][bcol] = bv;
        __syncthreads();
        #pragma unroll
        for (int kk = 0; kk < 8; kk++) {
            float af[8], bf[8];
            *(float4*)(af)     = *(const float4*)&As[kk][ms];
            *(float4*)(af + 4) = *(const float4*)&As[kk][ms + 4];
            *(float4*)(bf)     = *(const float4*)&Bs[kk][ns];
            *(float4*)(bf + 4) = *(const float4*)&Bs[kk][ns + 4];
            #pragma unroll
            for (int i = 0; i < 8; i++)
                #pragma unroll
                for (int j = 0; j < 8; j++)
                    acc[i][j] += af[i] * bf[j];
        }
    }

    #pragma unroll
    for (int i = 0; i < 8; i++) {
        size_t crow = (size_t)(bm + ms + i);
        #pragma unroll
        for (int j0 = 0; j0 < 8; j0 += 4) {
            float o[4];
            #pragma unroll
            for (int jj = 0; jj < 4; jj++) {
                int col = bn + ns + j0 + jj;
                float val = acc[i][j0 + jj] + bias[col];
                if (mode == 1)      val += res[crow * N + col];
                else if (mode == 2) val = 0.5f * val * (1.f + erff(val * 0.70710678118654752f));
                o[jj] = val;
            }
            *(float4*)(C + crow * N + bn + ns + j0) = *(float4*)o;
        }
    }
}

// ---------------- L1 distance -> raw scores: -lam/8 * sum_d |q-k| ----------------
// 64x64 tile per block, 256 threads, 4x4 microtile; smem stored d-major.
__global__ void __launch_bounds__(256) dist_kernel(
    const float* __restrict__ Q, const float* __restrict__ K,
    const float* __restrict__ lamp, float* __restrict__ attn)
{
    __shared__ float Qs[64][68];
    __shared__ float Ks[64][68];
    int bh = blockIdx.z;
    int b = bh / NHEAD, h = bh - b * NHEAD;
    const float* Qb = Q + (size_t)b * SEQ * HID + h * HDIM + (size_t)blockIdx.y * 64 * HID;
    const float* Kb = K + (size_t)b * SEQ * HID + h * HDIM + (size_t)blockIdx.x * 64 * HID;
    int tid = threadIdx.x;
    int row = tid >> 2, dg = (tid & 3) * 16;
    #pragma unroll
    for (int i = 0; i < 4; i++) {
        float4 qv = *(const float4*)(Qb + (size_t)row * HID + dg + i * 4);
        float4 kv = *(const float4*)(Kb + (size_t)row * HID + dg + i * 4);
        Qs[dg + i*4 + 0][row] = qv.x; Qs[dg + i*4 + 1][row] = qv.y;
        Qs[dg + i*4 + 2][row] = qv.z; Qs[dg + i*4 + 3][row] = qv.w;
        Ks[dg + i*4 + 0][row] = kv.x; Ks[dg + i*4 + 1][row] = kv.y;
        Ks[dg + i*4 + 2][row] = kv.z; Ks[dg + i*4 + 3][row] = kv.w;
    }
    __syncthreads();
    int tx = tid & 15, ty = tid >> 4;
    int qs = ty * 4, ks = tx * 4;
    float acc[4][4];
    #pragma unroll
    for (int i = 0; i < 4; i++)
        #pragma unroll
        for (int j = 0; j < 4; j++) acc[i][j] = 0.f;
    #pragma unroll 16
    for (int d = 0; d < HDIM; d++) {
        float4 qf = *(const float4*)&Qs[d][qs];
        float4 kf = *(const float4*)&Ks[d][ks];
        float qa[4] = {qf.x, qf.y, qf.z, qf.w};
        float ka[4] = {kf.x, kf.y, kf.z, kf.w};
        #pragma unroll
        for (int i = 0; i < 4; i++)
            #pragma unroll
            for (int j = 0; j < 4; j++)
                acc[i][j] += fabsf(qa[i] - ka[j]);
    }
    float c = -(*lamp) * 0.125f;  // scale = 1/sqrt(64)
    float* outp = attn + (size_t)bh * SEQ * SEQ
                + ((size_t)blockIdx.y * 64 + qs) * SEQ + blockIdx.x * 64 + ks;
    #pragma unroll
    for (int i = 0; i < 4; i++) {
        float4 o = make_float4(c * acc[i][0], c * acc[i][1], c * acc[i][2], c * acc[i][3]);
        *(float4*)(outp + (size_t)i * SEQ) = o;
    }
}

// ---------------- row softmax in place (rows of 1024) ----------------
__global__ void softmax_kernel(float* __restrict__ attn) {
    size_t row = blockIdx.x;
    float* p = attn + row * SEQ;
    int t = threadIdx.x;
    float4 v = *(float4*)(p + t * 4);
    __shared__ float sh[8];
    // max
    float mx = fmaxf(fmaxf(v.x, v.y), fmaxf(v.z, v.w));
    #pragma unroll
    for (int o = 16; o; o >>= 1) mx = fmaxf(mx, __shfl_xor_sync(0xffffffffu, mx, o));
    if (!(t & 31)) sh[t >> 5] = mx;
    __syncthreads();
    float m = sh[0];
    #pragma unroll
    for (int i = 1; i < 8; i++) m = fmaxf(m, sh[i]);
    __syncthreads();
    // exp + sum
    float4 e;
    e.x = expf(v.x - m); e.y = expf(v.y - m);
    e.z = expf(v.z - m); e.w = expf(v.w - m);
    float s = e.x + e.y + e.z + e.w;
    #pragma unroll
    for (int o = 16; o; o >>= 1) s += __shfl_xor_sync(0xffffffffu, s, o);
    if (!(t & 31)) sh[t >> 5] = s;
    __syncthreads();
    float tot = 0.f;
    #pragma unroll
    for (int i = 0; i < 8; i++) tot += sh[i];
    float inv = 1.f / tot;
    e.x *= inv; e.y *= inv; e.z *= inv; e.w *= inv;
    *(float4*)(p + t * 4) = e;
}

// ---------------- out = attn @ V per head, written merged-head [B,S,H] ----------------
__global__ void __launch_bounds__(256) pv_kernel(
    const float* __restrict__ attn, const float* __restrict__ V, float* __restrict__ O)
{
    int bh = blockIdx.z;
    int b = bh / NHEAD, h = bh - b * NHEAD;
    const float* Ab = attn + (size_t)bh * SEQ * SEQ + (size_t)blockIdx.x * 64 * SEQ;
    const float* Vb = V + (size_t)b * SEQ * HID + h * HDIM;
    float* Ob       = O + (size_t)b * SEQ * HID + h * HDIM + (size_t)blockIdx.x * 64 * HID;
    __shared__ float Sa[16][68];
    __shared__ float Sv[16][64];
    int tid = threadIdx.x;
    int ar = tid >> 2, ac = (tid & 3) * 4;     // attn tile 64q x 16k
    int vr = tid >> 4, vc = (tid & 15) * 4;    // V tile 16k x 64d
    int tx = tid & 15, ty = tid >> 4;
    int qs = ty * 4, ds = tx * 4;
    float acc[4][4];
    #pragma unroll
    for (int i = 0; i < 4; i++)
        #pragma unroll
        for (int j = 0; j < 4; j++) acc[i][j] = 0.f;

    for (int k0 = 0; k0 < SEQ; k0 += 16) {
        float4 a4 = *(const float4*)(Ab + (size_t)ar * SEQ + k0 + ac);
        float4 v4 = *(const float4*)(Vb + (size_t)(k0 + vr) * HID + vc);
        __syncthreads();
        Sa[ac + 0][ar] = a4.x; Sa[ac + 1][ar] = a4.y;
        Sa[ac + 2][ar] = a4.z; Sa[ac + 3][ar] = a4.w;
        *(float4*)&Sv[vr][vc] = v4;
        __syncthreads();
        #pragma unroll
        for (int kk = 0; kk < 16; kk++) {
            float4 af = *(const float4*)&Sa[kk][qs];
            float4 vf = *(const float4*)&Sv[kk][ds];
            float aa[4] = {af.x, af.y, af.z, af.w};
            float vv[4] = {vf.x, vf.y, vf.z, vf.w};
            #pragma unroll
            for (int i = 0; i < 4; i++)
                #pragma unroll
                for (int j = 0; j < 4; j++)
                    acc[i][j] += aa[i] * vv[j];
        }
    }
    #pragma unroll
    for (int i = 0; i < 4; i++) {
        float4 o = make_float4(acc[i][0], acc[i][1], acc[i][2], acc[i][3]);
        *(float4*)(Ob + (size_t)(qs + i) * HID + ds) = o;
    }
}

// ---------------- launch ----------------
extern "C" void kernel_launch(void* const* d_in, const int* in_sizes, int n_in,
                              void* d_out, int out_size) {
    const float* hidden = (const float*)d_in[0];
    const float* ln1g = (const float*)d_in[1];
    const float* ln1b = (const float*)d_in[2];
    const float* Wq = (const float*)d_in[3];
    const float* bq = (const float*)d_in[4];
    const float* Wk = (const float*)d_in[5];
    const float* bk = (const float*)d_in[6];
    const float* Wv = (const float*)d_in[7];
    const float* bv = (const float*)d_in[8];
    const float* Wo = (const float*)d_in[9];
    const float* bo = (const float*)d_in[10];
    const float* lam = (const float*)d_in[11];
    const float* ln2g = (const float*)d_in[12];
    const float* ln2b = (const float*)d_in[13];
    const float* W1 = (const float*)d_in[14];
    const float* b1 = (const float*)d_in[15];
    const float* W2 = (const float*)d_in[16];
    const float* b2 = (const float*)d_in[17];

    float* out0 = (float*)d_out;
    float* attn = out0 + (size_t)MTOT * HID;  // [B,NH,S,S] follows [B,S,H]

    float *x, *q, *k, *v, *ao, *r1, *y, *ff;
    cudaGetSymbolAddress((void**)&x,  g_x);
    cudaGetSymbolAddress((void**)&q,  g_q);
    cudaGetSymbolAddress((void**)&k,  g_k);
    cudaGetSymbolAddress((void**)&v,  g_v);
    cudaGetSymbolAddress((void**)&ao, g_ao);
    cudaGetSymbolAddress((void**)&r1, g_r1);
    cudaGetSymbolAddress((void**)&y,  g_y);
    cudaGetSymbolAddress((void**)&ff, g_ff);

    dim3 gHH(HID / 128, MTOT / 128);   // (6,16)
    dim3 gF1(FFD / 128, MTOT / 128);   // (24,16)

    ln_kernel<<<MTOT, 256>>>(hidden, ln1g, ln1b, x);
    sgemm_kernel<<<gHH, 256>>>(x, Wq, bq, nullptr, q, MTOT, HID, HID, 0);
    sgemm_kernel<<<gHH, 256>>>(x, Wk, bk, nullptr, k, MTOT, HID, HID, 0);
    sgemm_kernel<<<gHH, 256>>>(x, Wv, bv, nullptr, v, MTOT, HID, HID, 0);
    dist_kernel<<<dim3(SEQ / 64, SEQ / 64, BHTOT), 256>>>(q, k, lam, attn);
    softmax_kernel<<<BHTOT * SEQ, 256>>>(attn);
    pv_kernel<<<dim3(SEQ / 64, 1, BHTOT), 256>>>(attn, v, ao);
    sgemm_kernel<<<gHH, 256>>>(ao, Wo, bo, hidden, r1, MTOT, HID, HID, 1);
    ln_kernel<<<MTOT, 256>>>(r1, ln2g, ln2b, y);
    sgemm_kernel<<<gF1, 256>>>(y, W1, b1, nullptr, ff, MTOT, FFD, HID, 2);
    sgemm_kernel<<<gHH, 256>>>(ff, W2, b2, r1, out0, MTOT, HID, FFD, 1);
}

// round 2
// speedup vs baseline: 1.0024x; 1.0024x over previous
#include <cuda_runtime.h>
#include <math.h>

#define SEQ   1024
#define BATCH 2
#define HID   768
#define NHEAD 12
#define HDIM  64
#define FFD   3072
#define MTOT  (BATCH*SEQ)   // 2048
#define BHTOT (BATCH*NHEAD) // 24

// ---------------- scratch (device globals: no allocation allowed) ----------------
__device__ float g_x [MTOT*HID];
__device__ float g_q [MTOT*HID];
__device__ float g_k [MTOT*HID];
__device__ float g_v [MTOT*HID];
__device__ float g_ao[MTOT*HID];
__device__ float g_r1[MTOT*HID];
__device__ float g_y [MTOT*HID];
__device__ float g_ff[MTOT*FFD];

// ---------------- LayerNorm: one block per row of 768 ----------------
__global__ void ln_kernel(const float* __restrict__ in, const float* __restrict__ g,
                          const float* __restrict__ b, float* __restrict__ out) {
    int row = blockIdx.x;
    const float* x = in + (size_t)row * HID;
    int t = threadIdx.x;
    float v0 = x[t], v1 = x[t + 256], v2 = x[t + 512];
    float s  = v0 + v1 + v2;
    float sq = v0 * v0 + v1 * v1 + v2 * v2;
    __shared__ float sh[16];
    #pragma unroll
    for (int o = 16; o; o >>= 1) {
        s  += __shfl_xor_sync(0xffffffffu, s,  o);
        sq += __shfl_xor_sync(0xffffffffu, sq, o);
    }
    int w = t >> 5, l = t & 31;
    if (!l) { sh[w] = s; sh[w + 8] = sq; }
    __syncthreads();
    if (w == 0) {
        float a = (l < 8) ? sh[l] : 0.f;
        float c = (l < 8) ? sh[l + 8] : 0.f;
        #pragma unroll
        for (int o = 4; o; o >>= 1) {
            a += __shfl_xor_sync(0xffffffffu, a, o);
            c += __shfl_xor_sync(0xffffffffu, c, o);
        }
        if (!l) { sh[0] = a; sh[1] = c; }
    }
    __syncthreads();
    float mean = sh[0] * (1.f / HID);
    float var  = sh[1] * (1.f / HID) - mean * mean;
    float rs   = rsqrtf(var + 1e-5f);
    float* o = out + (size_t)row * HID;
    o[t]       = (v0 - mean) * rs * g[t]       + b[t];
    o[t + 256] = (v1 - mean) * rs * g[t + 256] + b[t + 256];
    o[t + 512] = (v2 - mean) * rs * g[t + 512] + b[t + 512];
}

// ---------------- sgemm: C = A[M,K] @ B[K,N] + bias (+res / gelu) ----------------
// BM=BN=128, BK=8, 256 threads, 8x8 microtile. M%128==0, N%128==0, K%8==0 required.
// mode: 0 = +bias, 1 = +bias+res, 2 = gelu(+bias)
__global__ void __launch_bounds__(256) sgemm_kernel(
    const float* __restrict__ A, const float* __restrict__ Bm,
    const float* __restrict__ bias, const float* __restrict__ res,
    float* __restrict__ C, int M, int N, int K, int mode)
{
    __shared__ float As[8][128];
    __shared__ float Bs[8][128];
    int tid = threadIdx.x;
    int bm = blockIdx.y * 128, bn = blockIdx.x * 128;
    int arow = tid >> 1, acol = (tid & 1) * 4;
    int brow = tid >> 5, bcol = (tid & 31) * 4;
    int tx = tid & 15, ty = tid >> 4;
    int ms = ty * 8, ns = tx * 8;

    float acc[8][8];
    #pragma unroll
    for (int i = 0; i < 8; i++)
        #pragma unroll
        for (int j = 0; j < 8; j++) acc[i][j] = 0.f;

    const float* Ap = A  + (size_t)(bm + arow) * K + acol;
    const float* Bp = Bm + (size_t)brow * N + bn + bcol;

    for (int k0 = 0; k0 < K; k0 += 8) {
        float4 av = *(const float4*)(Ap + k0);
        float4 bv = *(const float4*)(Bp + (size_t)k0 * N);
        __syncthreads();
        As[acol + 0][arow] = av.x;
        As[acol + 1][arow] = av.y;
        As[acol + 2][arow] = av.z;
        As[acol + 3][arow] = av.w;
        *(float4*)&Bs[brow][bcol] = bv;
        __syncthreads();
        #pragma unroll
        for (int kk = 0; kk < 8; kk++) {
            float af[8], bf[8];
            *(float4*)(af)     = *(const float4*)&As[kk][ms];
            *(float4*)(af + 4) = *(const float4*)&As[kk][ms + 4];
            *(float4*)(bf)     = *(const float4*)&Bs[kk][ns];
            *(float4*)(bf + 4) = *(const float4*)&Bs[kk][ns + 4];
            #pragma unroll
            for (int i = 0; i < 8; i++)
                #pragma unroll
                for (int j = 0; j < 8; j++)
                    acc[i][j] += af[i] * bf[j];
        }
    }

    #pragma unroll
    for (int i = 0; i < 8; i++) {
        size_t crow = (size_t)(bm + ms + i);
        #pragma unroll
        for (int j0 = 0; j0 < 8; j0 += 4) {
            float o[4];
            #pragma unroll
            for (int jj = 0; jj < 4; jj++) {
                int col = bn + ns + j0 + jj;
                float val = acc[i][j0 + jj] + bias[col];
                if (mode == 1)      val += res[crow * N + col];
                else if (mode == 2) val = 0.5f * val * (1.f + erff(val * 0.70710678118654752f));
                o[jj] = val;
            }
            *(float4*)(C + crow * N + bn + ns + j0) = *(float4*)o;
        }
    }
}

// ---------------- L1 distance -> raw scores: -lam/8 * sum_d |q-k| ----------------
// 64x64 tile per block, 256 threads, 4x4 microtile; smem stored d-major.
__global__ void __launch_bounds__(256) dist_kernel(
    const float* __restrict__ Q, const float* __restrict__ K,
    const float* __restrict__ lamp, float* __restrict__ attn)
{
    __shared__ float Qs[64][68];
    __shared__ float Ks[64][68];
    int bh = blockIdx.z;
    int b = bh / NHEAD, h = bh - b * NHEAD;
    const float* Qb = Q + (size_t)b * SEQ * HID + h * HDIM + (size_t)blockIdx.y * 64 * HID;
    const float* Kb = K + (size_t)b * SEQ * HID + h * HDIM + (size_t)blockIdx.x * 64 * HID;
    int tid = threadIdx.x;
    int row = tid >> 2, dg = (tid & 3) * 16;
    #pragma unroll
    for (int i = 0; i < 4; i++) {
        float4 qv = *(const float4*)(Qb + (size_t)row * HID + dg + i * 4);
        float4 kv = *(const float4*)(Kb + (size_t)row * HID + dg + i * 4);
        Qs[dg + i*4 + 0][row] = qv.x; Qs[dg + i*4 + 1][row] = qv.y;
        Qs[dg + i*4 + 2][row] = qv.z; Qs[dg + i*4 + 3][row] = qv.w;
        Ks[dg + i*4 + 0][row] = kv.x; Ks[dg + i*4 + 1][row] = kv.y;
        Ks[dg + i*4 + 2][row] = kv.z; Ks[dg + i*4 + 3][row] = kv.w;
    }
    __syncthreads();
    int tx = tid & 15, ty = tid >> 4;
    int qs = ty * 4, ks = tx * 4;
    float acc[4][4];
    #pragma unroll
    for (int i = 0; i < 4; i++)
        #pragma unroll
        for (int j = 0; j < 4; j++) acc[i][j] = 0.f;
    #pragma unroll 16
    for (int d = 0; d < HDIM; d++) {
        float4 qf = *(const float4*)&Qs[d][qs];
        float4 kf = *(const float4*)&Ks[d][ks];
        float qa[4] = {qf.x, qf.y, qf.z, qf.w};
        float ka[4] = {kf.x, kf.y, kf.z, kf.w};
        #pragma unroll
        for (int i = 0; i < 4; i++)
            #pragma unroll
            for (int j = 0; j < 4; j++)
                acc[i][j] += fabsf(qa[i] - ka[j]);
    }
    float c = -(*lamp) * 0.125f;  // scale = 1/sqrt(64)
    float* outp = attn + (size_t)bh * SEQ * SEQ
                + ((size_t)blockIdx.y * 64 + qs) * SEQ + blockIdx.x * 64 + ks;
    #pragma unroll
    for (int i = 0; i < 4; i++) {
        float4 o = make_float4(c * acc[i][0], c * acc[i][1], c * acc[i][2], c * acc[i][3]);
        *(float4*)(outp + (size_t)i * SEQ) = o;
    }
}

// ---------------- row softmax in place (rows of 1024) ----------------
__global__ void softmax_kernel(float* __restrict__ attn) {
    size_t row = blockIdx.x;
    float* p = attn + row * SEQ;
    int t = threadIdx.x;
    float4 v = *(float4*)(p + t * 4);
    __shared__ float sh[8];
    // max
    float mx = fmaxf(fmaxf(v.x, v.y), fmaxf(v.z, v.w));
    #pragma unroll
    for (int o = 16; o; o >>= 1) mx = fmaxf(mx, __shfl_xor_sync(0xffffffffu, mx, o));
    if (!(t & 31)) sh[t >> 5] = mx;
    __syncthreads();
    float m = sh[0];
    #pragma unroll
    for (int i = 1; i < 8; i++) m = fmaxf(m, sh[i]);
    __syncthreads();
    // exp + sum
    float4 e;
    e.x = expf(v.x - m); e.y = expf(v.y - m);
    e.z = expf(v.z - m); e.w = expf(v.w - m);
    float s = e.x + e.y + e.z + e.w;
    #pragma unroll
    for (int o = 16; o; o >>= 1) s += __shfl_xor_sync(0xffffffffu, s, o);
    if (!(t & 31)) sh[t >> 5] = s;
    __syncthreads();
    float tot = 0.f;
    #pragma unroll
    for (int i = 0; i < 8; i++) tot += sh[i];
    float inv = 1.f / tot;
    e.x *= inv; e.y *= inv; e.z *= inv; e.w *= inv;
    *(float4*)(p + t * 4) = e;
}

// ---------------- out = attn @ V per head, written merged-head [B,S,H] ----------------
__global__ void __launch_bounds__(256) pv_kernel(
    const float* __restrict__ attn, const float* __restrict__ V, float* __restrict__ O)
{
    int bh = blockIdx.z;
    int b = bh / NHEAD, h = bh - b * NHEAD;
    const float* Ab = attn + (size_t)bh * SEQ * SEQ + (size_t)blockIdx.x * 64 * SEQ;
    const float* Vb = V + (size_t)b * SEQ * HID + h * HDIM;
    float* Ob       = O + (size_t)b * SEQ * HID + h * HDIM + (size_t)blockIdx.x * 64 * HID;
    __shared__ float Sa[16][68];
    __shared__ float Sv[16][64];
    int tid = threadIdx.x;
    int ar = tid >> 2, ac = (tid & 3) * 4;     // attn tile 64q x 16k
    int vr = tid >> 4, vc = (tid & 15) * 4;    // V tile 16k x 64d
    int tx = tid & 15, ty = tid >> 4;
    int qs = ty * 4, ds = tx * 4;
    float acc[4][4];
    #pragma unroll
    for (int i = 0; i < 4; i++)
        #pragma unroll
        for (int j = 0; j < 4; j++) acc[i][j] = 0.f;

    for (int k0 = 0; k0 < SEQ; k0 += 16) {
        float4 a4 = *(const float4*)(Ab + (size_t)ar * SEQ + k0 + ac);
        float4 v4 = *(const float4*)(Vb + (size_t)(k0 + vr) * HID + vc);
        __syncthreads();
        Sa[ac + 0][ar] = a4.x; Sa[ac + 1][ar] = a4.y;
        Sa[ac + 2][ar] = a4.z; Sa[ac + 3][ar] = a4.w;
        *(float4*)&Sv[vr][vc] = v4;
        __syncthreads();
        #pragma unroll
        for (int kk = 0; kk < 16; kk++) {
            float4 af = *(const float4*)&Sa[kk][qs];
            float4 vf = *(const float4*)&Sv[kk][ds];
            float aa[4] = {af.x, af.y, af.z, af.w};
            float vv[4] = {vf.x, vf.y, vf.z, vf.w};
            #pragma unroll
            for (int i = 0; i < 4; i++)
                #pragma unroll
                for (int j = 0; j < 4; j++)
                    acc[i][j] += aa[i] * vv[j];
        }
    }
    #pragma unroll
    for (int i = 0; i < 4; i++) {
        float4 o = make_float4(acc[i][0], acc[i][1], acc[i][2], acc[i][3]);
        *(float4*)(Ob + (size_t)(qs + i) * HID + ds) = o;
    }
}

// ---------------- launch ----------------
extern "C" void kernel_launch(void* const* d_in, const int* in_sizes, int n_in,
                              void* d_out, int out_size) {
    const float* hidden = (const float*)d_in[0];
    const float* ln1g = (const float*)d_in[1];
    const float* ln1b = (const float*)d_in[2];
    const float* Wq = (const float*)d_in[3];
    const float* bq = (const float*)d_in[4];
    const float* Wk = (const float*)d_in[5];
    const float* bk = (const float*)d_in[6];
    const float* Wv = (const float*)d_in[7];
    const float* bv = (const float*)d_in[8];
    const float* Wo = (const float*)d_in[9];
    const float* bo = (const float*)d_in[10];
    const float* lam = (const float*)d_in[11];
    const float* ln2g = (const float*)d_in[12];
    const float* ln2b = (const float*)d_in[13];
    const float* W1 = (const float*)d_in[14];
    const float* b1 = (const float*)d_in[15];
    const float* W2 = (const float*)d_in[16];
    const float* b2 = (const float*)d_in[17];

    float* out0 = (float*)d_out;
    float* attn = out0 + (size_t)MTOT * HID;  // [B,NH,S,S] follows [B,S,H]

    float *x, *q, *k, *v, *ao, *r1, *y, *ff;
    cudaGetSymbolAddress((void**)&x,  g_x);
    cudaGetSymbolAddress((void**)&q,  g_q);
    cudaGetSymbolAddress((void**)&k,  g_k);
    cudaGetSymbolAddress((void**)&v,  g_v);
    cudaGetSymbolAddress((void**)&ao, g_ao);
    cudaGetSymbolAddress((void**)&r1, g_r1);
    cudaGetSymbolAddress((void**)&y,  g_y);
    cudaGetSymbolAddress((void**)&ff, g_ff);

    dim3 gHH(HID / 128, MTOT / 128);   // (6,16)
    dim3 gF1(FFD / 128, MTOT / 128);   // (24,16)

    ln_kernel<<<MTOT, 256>>>(hidden, ln1g, ln1b, x);
    sgemm_kernel<<<gHH, 256>>>(x, Wq, bq, nullptr, q, MTOT, HID, HID, 0);
    sgemm_kernel<<<gHH, 256>>>(x, Wk, bk, nullptr, k, MTOT, HID, HID, 0);
    sgemm_kernel<<<gHH, 256>>>(x, Wv, bv, nullptr, v, MTOT, HID, HID, 0);
    dist_kernel<<<dim3(SEQ / 64, SEQ / 64, BHTOT), 256>>>(q, k, lam, attn);
    softmax_kernel<<<BHTOT * SEQ, 256>>>(attn);
    pv_kernel<<<dim3(SEQ / 64, 1, BHTOT), 256>>>(attn, v, ao);
    sgemm_kernel<<<gHH, 256>>>(ao, Wo, bo, hidden, r1, MTOT, HID, HID, 1);
    ln_kernel<<<MTOT, 256>>>(r1, ln2g, ln2b, y);
    sgemm_kernel<<<gF1, 256>>>(y, W1, b1, nullptr, ff, MTOT, FFD, HID, 2);
    sgemm_kernel<<<gHH, 256>>>(ff, W2, b2, r1, out0, MTOT, HID, FFD, 1);
}